// round 1
// baseline (speedup 1.0000x reference)
#include <cuda_runtime.h>
#include <math.h>
#include <string.h>

// Problem constants
#define DD    2560
#define HDIM  320
#define NH    8
#define SEGL  1024
#define STOT  4096
#define BATCH 2
#define MMEM  128
#define NSEG  4
#define BKK   16

// -------------------------- scratch (device globals, no allocation) ---------
__device__ float g_qr  [BATCH*SEGL*DD];
__device__ float g_ctx [BATCH*SEGL*DD];
__device__ float g_gate[BATCH*SEGL*DD];
__device__ float g_kw  [BATCH*SEGL*DD];
__device__ float g_vw  [BATCH*SEGL*DD];
__device__ float g_memA[BATCH*MMEM*DD];
__device__ float g_memB[BATCH*MMEM*DD];
__device__ float g_kr  [BATCH*MMEM*DD];
__device__ float g_vr  [BATCH*MMEM*DD];
__device__ float g_qw  [BATCH*MMEM*DD];
__device__ float g_aw  [BATCH*MMEM*DD];
__device__ float g_nm  [BATCH*MMEM*DD];
__device__ float g_cat [BATCH*MMEM*2*DD];

// -------------------------- f32x2 packed helpers ----------------------------
__device__ __forceinline__ unsigned long long fma2(unsigned long long a,
                                                   unsigned long long b,
                                                   unsigned long long c) {
    unsigned long long d;
    asm("fma.rn.f32x2 %0, %1, %2, %3;" : "=l"(d) : "l"(a), "l"(b), "l"(c));
    return d;
}
__device__ __forceinline__ unsigned long long dup2(float x) {
    unsigned long long d;
    asm("mov.b64 %0, {%1, %1};" : "=l"(d) : "r"(__float_as_uint(x)));
    return d;
}
__device__ __forceinline__ float sigmoidf_(float x) {
    return 1.0f / (1.0f + __expf(-x));
}

// -------------------------- tiled GEMM, C = A @ W (+epilogue) ---------------
// A: (M,K) row-major with chunked row mapping: grow(m) = (m/a_cr)*a_cs + m%a_cr
// W: (K,N) row-major (dense). C: (M,N) with its own chunk mapping.
// EPI 0: C = acc
// EPI 1: C = sigmoid(acc + aux0[n])                         (gate)
// EPI 2: C = aux1[c-mapped] + aux2[contig]*acc              (h = seg + gate*proj)
// EPI 3: s = sigmoid(acc + aux0[n]); C = s*aux1 + (1-s)*aux2 (memory gate)
template<int BM, int BN, int TM, int TN, int EPI>
__launch_bounds__(256)
__global__ void gemm_k(const float* __restrict__ A, const float* __restrict__ W,
                       float* __restrict__ C, int M, int N, int K,
                       int a_cr, long long a_cs, int c_cr, long long c_cs,
                       const float* __restrict__ aux0,
                       const float* __restrict__ aux1,
                       const float* __restrict__ aux2) {
    __shared__ float As[BKK][BM + 1];
    __shared__ float Bs[BKK][BN];

    const int tid = threadIdx.x;
    const int tx  = tid % (BN / TN);
    const int ty  = tid / (BN / TN);
    const int m0  = blockIdx.y * BM;
    const int n0  = blockIdx.x * BN;

    const long long arow = (long long)(m0 / a_cr) * a_cs + (m0 % a_cr);
    const float* Abase = A + arow * (long long)K;

    unsigned long long acc[TM][TN / 2];
#pragma unroll
    for (int i = 0; i < TM; ++i)
#pragma unroll
        for (int j = 0; j < TN / 2; ++j) acc[i][j] = 0ULL;

    const unsigned long long* Bs64 =
        reinterpret_cast<const unsigned long long*>(&Bs[0][0]);

    for (int k0 = 0; k0 < K; k0 += BKK) {
        // cooperative loads
        constexpr int AE = (BM * BKK) / 256;
#pragma unroll
        for (int t = 0; t < AE; ++t) {
            int idx = tid + t * 256;
            int r = idx / BKK, c = idx % BKK;
            As[c][r] = Abase[(long long)r * K + k0 + c];
        }
        constexpr int BE = (BKK * BN) / 256;
#pragma unroll
        for (int t = 0; t < BE; ++t) {
            int idx = tid + t * 256;
            int kr = idx / BN, nc = idx % BN;
            Bs[kr][nc] = W[(long long)(k0 + kr) * N + n0 + nc];
        }
        __syncthreads();

#pragma unroll
        for (int kk = 0; kk < BKK; ++kk) {
            unsigned long long bv[TN / 2];
#pragma unroll
            for (int j = 0; j < TN / 2; ++j)
                bv[j] = Bs64[(kk * BN + tx * TN) / 2 + j];
#pragma unroll
            for (int i = 0; i < TM; ++i) {
                unsigned long long av = dup2(As[kk][ty * TM + i]);
#pragma unroll
                for (int j = 0; j < TN / 2; ++j)
                    acc[i][j] = fma2(av, bv[j], acc[i][j]);
            }
        }
        __syncthreads();
    }

    // epilogue
    const long long crow = (long long)(m0 / c_cr) * c_cs + (m0 % c_cr);
#pragma unroll
    for (int i = 0; i < TM; ++i) {
        const int mr = ty * TM + i;
        const long long cidx = (crow + mr) * (long long)N;
        const long long lidx = (long long)(m0 + mr) * (long long)N;
#pragma unroll
        for (int j = 0; j < TN / 2; ++j) {
            float2 v;
            memcpy(&v, &acc[i][j], 8);
            const int nbase = n0 + tx * TN + 2 * j;
            float vals[2] = {v.x, v.y};
#pragma unroll
            for (int e = 0; e < 2; ++e) {
                const int nn = nbase + e;
                const float a = vals[e];
                if (EPI == 0) {
                    C[cidx + nn] = a;
                } else if (EPI == 1) {
                    C[cidx + nn] = sigmoidf_(a + aux0[nn]);
                } else if (EPI == 2) {
                    C[cidx + nn] = aux1[cidx + nn] + aux2[lidx + nn] * a;
                } else {
                    float s = sigmoidf_(a + aux0[nn]);
                    C[cidx + nn] = s * aux1[cidx + nn] + (1.0f - s) * aux2[cidx + nn];
                }
            }
        }
    }
}

// -------------------------- attention: one block per (q, head, batch) -------
__global__ void attn_k(const float* __restrict__ Q, const float* __restrict__ Km,
                       const float* __restrict__ V, float* __restrict__ O,
                       int Lq, int Lk, float scale) {
    const int q = blockIdx.x, h = blockIdx.y, b = blockIdx.z;
    const int tid = threadIdx.x;  // 128 threads

    __shared__ float qs[HDIM];
    __shared__ float sc[1024];
    __shared__ float red[128];

    const float* qp = Q + ((long long)(b * Lq + q)) * DD + h * HDIM;
    for (int d = tid; d < HDIM; d += 128) qs[d] = qp[d];
    __syncthreads();

    const float4* q4 = reinterpret_cast<const float4*>(qs);

    float lmax = -1e30f;
    for (int j = tid; j < Lk; j += 128) {
        const float4* k4 = reinterpret_cast<const float4*>(
            Km + ((long long)(b * Lk + j)) * DD + h * HDIM);
        float s = 0.0f;
#pragma unroll 8
        for (int d = 0; d < HDIM / 4; ++d) {
            float4 a = q4[d], kb = k4[d];
            s += a.x * kb.x + a.y * kb.y + a.z * kb.z + a.w * kb.w;
        }
        s *= scale;
        sc[j] = s;
        lmax = fmaxf(lmax, s);
    }
    red[tid] = lmax;
    __syncthreads();
    for (int o = 64; o > 0; o >>= 1) {
        if (tid < o) red[tid] = fmaxf(red[tid], red[tid + o]);
        __syncthreads();
    }
    const float gmax = red[0];
    __syncthreads();

    float lsum = 0.0f;
    for (int j = tid; j < Lk; j += 128) {
        float e = __expf(sc[j] - gmax);
        sc[j] = e;
        lsum += e;
    }
    red[tid] = lsum;
    __syncthreads();
    for (int o = 64; o > 0; o >>= 1) {
        if (tid < o) red[tid] += red[tid + o];
        __syncthreads();
    }
    const float inv = 1.0f / red[0];
    __syncthreads();

    float* op = O + ((long long)(b * Lq + q)) * DD + h * HDIM;
    for (int d = tid; d < HDIM; d += 128) {
        float acc = 0.0f;
        const float* vp = V + ((long long)b * Lk) * DD + h * HDIM + d;
        for (int j = 0; j < Lk; ++j) acc += sc[j] * vp[(long long)j * DD];
        op[d] = acc * inv;
    }
}

// -------------------------- concat [mem, new_mem] along features ------------
__global__ void concat_k(const float* __restrict__ a, const float* __restrict__ b,
                         float* __restrict__ c, int rows, int d) {
    int idx = blockIdx.x * blockDim.x + threadIdx.x;
    int total = rows * 2 * d;
    if (idx >= total) return;
    int r = idx / (2 * d);
    int col = idx % (2 * d);
    c[idx] = (col < d) ? a[(long long)r * d + col] : b[(long long)r * d + col - d];
}

// -------------------------- host orchestration ------------------------------
extern "C" void kernel_launch(void* const* d_in, const int* in_sizes, int n_in,
                              void* d_out, int out_size) {
    const float* hid      = (const float*)d_in[0];
    const float* init_mem = (const float*)d_in[1];
    const float* wq_r     = (const float*)d_in[2];
    const float* wk_r     = (const float*)d_in[3];
    const float* wv_r     = (const float*)d_in[4];
    const float* wo_r     = (const float*)d_in[5];
    const float* wg_r     = (const float*)d_in[6];
    const float* bg_r     = (const float*)d_in[7];
    const float* wqueries = (const float*)d_in[8];
    const float* wq_w     = (const float*)d_in[9];
    const float* wk_w     = (const float*)d_in[10];
    const float* wv_w     = (const float*)d_in[11];
    const float* wo_w     = (const float*)d_in[12];
    const float* wg_w     = (const float*)d_in[13];
    const float* bg_w     = (const float*)d_in[14];
    float* out = (float*)d_out;

    float *qr, *ctx, *gate, *kw, *vw, *memA, *memB, *kr, *vr, *qw, *aw, *nm, *cat;
    cudaGetSymbolAddress((void**)&qr,   g_qr);
    cudaGetSymbolAddress((void**)&ctx,  g_ctx);
    cudaGetSymbolAddress((void**)&gate, g_gate);
    cudaGetSymbolAddress((void**)&kw,   g_kw);
    cudaGetSymbolAddress((void**)&vw,   g_vw);
    cudaGetSymbolAddress((void**)&memA, g_memA);
    cudaGetSymbolAddress((void**)&memB, g_memB);
    cudaGetSymbolAddress((void**)&kr,   g_kr);
    cudaGetSymbolAddress((void**)&vr,   g_vr);
    cudaGetSymbolAddress((void**)&qw,   g_qw);
    cudaGetSymbolAddress((void**)&aw,   g_aw);
    cudaGetSymbolAddress((void**)&nm,   g_nm);
    cudaGetSymbolAddress((void**)&cat,  g_cat);

    const float scale = 0.05590169943749474f;  // 1/sqrt(320)
    const size_t memBytes = (size_t)MMEM * DD * sizeof(float);
    const int MBIG = BATCH * SEGL;   // 2048
    const int MSM  = BATCH * MMEM;   // 256

    // dim3 helpers
    dim3 gBig(DD / 128, MBIG / 64);       // big GEMM grid (20, 32)
    dim3 gSm (DD / 64,  MSM / 32);        // small GEMM grid (40, 8)
    dim3 gQw (DD / 64,  MMEM / 32);       // q_w grid       (40, 4)

    // --- pre-loop: q_w = write_queries @ wq_w, duplicated for batch 1 -------
    gemm_k<32, 64, 2, 4, 0><<<gQw, 256>>>(wqueries, wq_w, qw, MMEM, DD, DD,
                                          MMEM, MMEM, MMEM, MMEM,
                                          nullptr, nullptr, nullptr);
    cudaMemcpyAsync(qw + (size_t)MMEM * DD, qw, memBytes,
                    cudaMemcpyDeviceToDevice, 0);

    // --- initial memory broadcast to (B, M, D) ------------------------------
    cudaMemcpyAsync(memB, init_mem, memBytes, cudaMemcpyDeviceToDevice, 0);
    cudaMemcpyAsync(memB + (size_t)MMEM * DD, init_mem, memBytes,
                    cudaMemcpyDeviceToDevice, 0);

    float* mem_cur = memB;

    for (int i = 0; i < NSEG; ++i) {
        const float* segp = hid + (long long)i * SEGL * DD;
        float* outp = out + (long long)i * SEGL * DD;

        // 1. q_r = seg @ wq_r  (A chunked: chunk 1024 rows, stride 4096 rows)
        gemm_k<64, 128, 4, 8, 0><<<gBig, 256>>>(segp, wq_r, qr, MBIG, DD, DD,
                                                SEGL, STOT, MBIG, MBIG,
                                                nullptr, nullptr, nullptr);
        // 2-3. k_r, v_r = mem @ wk_r / wv_r
        gemm_k<32, 64, 2, 4, 0><<<gSm, 256>>>(mem_cur, wk_r, kr, MSM, DD, DD,
                                              MSM, MSM, MSM, MSM,
                                              nullptr, nullptr, nullptr);
        gemm_k<32, 64, 2, 4, 0><<<gSm, 256>>>(mem_cur, wv_r, vr, MSM, DD, DD,
                                              MSM, MSM, MSM, MSM,
                                              nullptr, nullptr, nullptr);
        // 4. read attention -> ctx
        attn_k<<<dim3(SEGL, NH, BATCH), 128>>>(qr, kr, vr, ctx, SEGL, MMEM, scale);
        // 5. gate = sigmoid(seg @ wg_r + bg_r)
        gemm_k<64, 128, 4, 8, 1><<<gBig, 256>>>(segp, wg_r, gate, MBIG, DD, DD,
                                                SEGL, STOT, MBIG, MBIG,
                                                bg_r, nullptr, nullptr);
        // 6. h = seg + gate * (ctx @ wo_r)  -> written straight into d_out
        gemm_k<64, 128, 4, 8, 2><<<gBig, 256>>>(ctx, wo_r, outp, MBIG, DD, DD,
                                                MBIG, MBIG, SEGL, STOT,
                                                nullptr, segp, gate);
        // 7-8. k_w, v_w = h @ wk_w / wv_w  (A = out, chunked)
        gemm_k<64, 128, 4, 8, 0><<<gBig, 256>>>(outp, wk_w, kw, MBIG, DD, DD,
                                                SEGL, STOT, MBIG, MBIG,
                                                nullptr, nullptr, nullptr);
        gemm_k<64, 128, 4, 8, 0><<<gBig, 256>>>(outp, wv_w, vw, MBIG, DD, DD,
                                                SEGL, STOT, MBIG, MBIG,
                                                nullptr, nullptr, nullptr);
        // 9. write attention -> aw
        attn_k<<<dim3(MMEM, NH, BATCH), 128>>>(qw, kw, vw, aw, MMEM, SEGL, scale);
        // 10. new_mem = aw @ wo_w
        gemm_k<32, 64, 2, 4, 0><<<gSm, 256>>>(aw, wo_w, nm, MSM, DD, DD,
                                              MSM, MSM, MSM, MSM,
                                              nullptr, nullptr, nullptr);
        // 11. memory update
        if (i == 0) {
            cudaMemcpyAsync(memA, nm, (size_t)MSM * DD * sizeof(float),
                            cudaMemcpyDeviceToDevice, 0);
            mem_cur = memA;
        } else {
            float* mem_next = (mem_cur == memA) ? memB : memA;
            int total = MSM * 2 * DD;
            concat_k<<<(total + 255) / 256, 256>>>(mem_cur, nm, cat, MSM, DD);
            gemm_k<32, 64, 2, 4, 3><<<gSm, 256>>>(cat, wg_w, mem_next,
                                                  MSM, DD, 2 * DD,
                                                  MSM, MSM, MSM, MSM,
                                                  bg_w, nm, mem_cur);
            mem_cur = mem_next;
        }
    }
}

// round 2
// speedup vs baseline: 3.8158x; 3.8158x over previous
#include <cuda_runtime.h>
#include <cuda_bf16.h>
#include <math.h>
#include <stdint.h>

// Problem constants
#define DD    2560
#define HDIM  320
#define NH    8
#define SEGL  1024
#define STOT  4096
#define BATCH 2
#define MMEM  128
#define NSEG  4
#define BKT   32          // GEMM K tile

// ---------------- fp32 scratch ----------------------------------------------
__device__ float g_qr  [BATCH*SEGL*DD];
__device__ float g_ctx [BATCH*SEGL*DD];
__device__ float g_gate[BATCH*SEGL*DD];
__device__ float g_kw  [BATCH*SEGL*DD];
__device__ float g_vw  [BATCH*SEGL*DD];
__device__ float g_memA[BATCH*MMEM*DD];
__device__ float g_memB[BATCH*MMEM*DD];
__device__ float g_kr  [BATCH*MMEM*DD];
__device__ float g_vr  [BATCH*MMEM*DD];
__device__ float g_qw  [BATCH*MMEM*DD];
__device__ float g_aw  [BATCH*MMEM*DD];
__device__ float g_nm  [BATCH*MMEM*DD];
__device__ float g_cat [BATCH*MMEM*2*DD];

// ---------------- bf16 split scratch (16B aligned for cp.async) -------------
#define WMAT (DD*DD)                    // 6,553,600
#define WTOT (9*WMAT + 2*WMAT)          // 9 DxD + one 2DxD = 72,089,600
__device__ __align__(16) __nv_bfloat16 g_whi[WTOT];
__device__ __align__(16) __nv_bfloat16 g_wlo[WTOT];
__device__ __align__(16) __nv_bfloat16 g_ahi[BATCH*SEGL*DD];
__device__ __align__(16) __nv_bfloat16 g_alo[BATCH*SEGL*DD];
__device__ __align__(16) __nv_bfloat16 g_chi[BATCH*SEGL*DD];
__device__ __align__(16) __nv_bfloat16 g_clo[BATCH*SEGL*DD];
__device__ __align__(16) __nv_bfloat16 g_shi[BATCH*MMEM*2*DD];
__device__ __align__(16) __nv_bfloat16 g_slo[BATCH*MMEM*2*DD];

// weight offsets (elements)
#define OW_QR (0LL*WMAT)
#define OW_KR (1LL*WMAT)
#define OW_VR (2LL*WMAT)
#define OW_OR (3LL*WMAT)
#define OW_GR (4LL*WMAT)
#define OW_QW (5LL*WMAT)
#define OW_KW (6LL*WMAT)
#define OW_VW (7LL*WMAT)
#define OW_OW (8LL*WMAT)
#define OW_GW (9LL*WMAT)

// ---------------- PTX helpers -----------------------------------------------
__device__ __forceinline__ void cp16(uint32_t s, const void* g) {
    asm volatile("cp.async.cg.shared.global [%0], [%1], 16;\n" :: "r"(s), "l"(g));
}
__device__ __forceinline__ void cp_commit() {
    asm volatile("cp.async.commit_group;\n");
}
__device__ __forceinline__ void ldsm4(uint32_t& r0, uint32_t& r1, uint32_t& r2,
                                      uint32_t& r3, uint32_t a) {
    asm volatile("ldmatrix.sync.aligned.m8n8.x4.shared.b16 {%0,%1,%2,%3}, [%4];"
                 : "=r"(r0), "=r"(r1), "=r"(r2), "=r"(r3) : "r"(a));
}
__device__ __forceinline__ void ldsm4t(uint32_t& r0, uint32_t& r1, uint32_t& r2,
                                       uint32_t& r3, uint32_t a) {
    asm volatile("ldmatrix.sync.aligned.m8n8.x4.trans.shared.b16 {%0,%1,%2,%3}, [%4];"
                 : "=r"(r0), "=r"(r1), "=r"(r2), "=r"(r3) : "r"(a));
}
__device__ __forceinline__ void mma16816(float* c, const uint32_t* a, const uint32_t* b) {
    asm volatile("mma.sync.aligned.m16n8k16.row.col.f32.bf16.bf16.f32 "
                 "{%0,%1,%2,%3}, {%4,%5,%6,%7}, {%8,%9}, {%0,%1,%2,%3};"
                 : "+f"(c[0]), "+f"(c[1]), "+f"(c[2]), "+f"(c[3])
                 : "r"(a[0]), "r"(a[1]), "r"(a[2]), "r"(a[3]),
                   "r"(b[0]), "r"(b[1]));
}
__device__ __forceinline__ float sigmoidf_(float x) {
    return 1.0f / (1.0f + __expf(-x));
}

// ---------------- split kernel: fp32 -> bf16 hi/lo (optional row chunking) --
__global__ void split2d(const float* __restrict__ x, __nv_bfloat16* __restrict__ hi,
                        __nv_bfloat16* __restrict__ lo, int Kd, int a_cr,
                        long long a_cs) {
    const int m = blockIdx.y;
    const int k = blockIdx.x * blockDim.x + threadIdx.x;
    if (k >= Kd) return;
    const long long srow = (long long)(m / a_cr) * a_cs + (m % a_cr);
    const float v = x[srow * (long long)Kd + k];
    const __nv_bfloat16 h = __float2bfloat16(v);
    const float r = v - __bfloat162float(h);
    const long long o = (long long)m * Kd + k;
    hi[o] = h;
    lo[o] = __float2bfloat16(r);
}

// ---------------- bf16-split tensor-core GEMM -------------------------------
// C(M,N) = (Ah+Al)(Wh) + Ah(Wl), fp32 accumulate.
// A dense (M,K) bf16. W (K,N) bf16. C rows chunk-mapped: (m/c_cr)*c_cs + m%c_cr.
// EPI 0: C = acc
// EPI 1: C = sigmoid(acc + aux0[n])
// EPI 2: C = aux1[ci] + aux2[li]*acc
// EPI 3: s = sigmoid(acc + aux0[n]); C = s*aux1[ci] + (1-s)*aux2[ci]
template<int BM, int BN, int WM, int WN, int EPI>
__global__ void __launch_bounds__(256)
mma_gemm(const __nv_bfloat16* __restrict__ Ah, const __nv_bfloat16* __restrict__ Al,
         const __nv_bfloat16* __restrict__ Wh, const __nv_bfloat16* __restrict__ Wl,
         float* __restrict__ C, int M, int N, int K,
         int c_cr, long long c_cs,
         const float* __restrict__ aux0, const float* __restrict__ aux1,
         const float* __restrict__ aux2) {
    constexpr int A_ROWB = BKT * 2 + 16;           // 80 bytes, conflict-free
    constexpr int B_ROWB = BN * 2 + 16;            // 272 bytes
    constexpr int A_TILE = BM * A_ROWB;
    constexpr int B_TILE = BKT * B_ROWB;
    constexpr int STAGE  = 2 * A_TILE + 2 * B_TILE;
    constexpr int MT = WM / 16, NT = WN / 8;
    constexpr int WN_CNT = BN / WN;

    extern __shared__ char smem_raw[];
    const uint32_t sbase = (uint32_t)__cvta_generic_to_shared(smem_raw);

    const int tid  = threadIdx.x;
    const int m0   = blockIdx.y * BM;
    const int n0   = blockIdx.x * BN;
    const int warp = tid >> 5, lane = tid & 31;
    const int wid_m = warp / WN_CNT, wid_n = warp % WN_CNT;

    float acc[MT][NT][4];
#pragma unroll
    for (int i = 0; i < MT; ++i)
#pragma unroll
        for (int j = 0; j < NT; ++j)
#pragma unroll
            for (int e = 0; e < 4; ++e) acc[i][j][e] = 0.0f;

    const int NKI = K / BKT;

    auto load_stage = [&](int ks, int st) {
        const int k0 = ks * BKT;
        const uint32_t sb = sbase + st * STAGE;
#pragma unroll
        for (int t = 0; t < (BM * 4) / 256; ++t) {
            const int c = tid + t * 256;
            const int r = c >> 2, kc = (c & 3) * 8;
            const uint32_t off = r * A_ROWB + kc * 2;
            const long long gi = (long long)(m0 + r) * K + k0 + kc;
            cp16(sb + off, Ah + gi);
            cp16(sb + A_TILE + off, Al + gi);
        }
#pragma unroll
        for (int t = 0; t < 2; ++t) {
            const int c = tid + t * 256;
            const int r = c >> 4, nc = (c & 15) * 8;
            const uint32_t off = 2 * A_TILE + r * B_ROWB + nc * 2;
            const long long gi = (long long)(k0 + r) * N + n0 + nc;
            cp16(sb + off, Wh + gi);
            cp16(sb + B_TILE + off, Wl + gi);
        }
        cp_commit();
    };

    load_stage(0, 0);
    load_stage(1, 1);

    for (int ks = 0; ks < NKI; ++ks) {
        if (ks < NKI - 1) {
            asm volatile("cp.async.wait_group 1;\n");
        } else {
            asm volatile("cp.async.wait_group 0;\n");
        }
        __syncthreads();
        const uint32_t sb = sbase + (ks % 3) * STAGE;

#pragma unroll
        for (int kk = 0; kk < BKT; kk += 16) {
            uint32_t ah[MT][4], al[MT][4], bh[NT][2], bl[NT][2];
            const int arow = wid_m * WM + (lane & 15);
            const int acol = kk + (lane >> 4) * 8;
#pragma unroll
            for (int i = 0; i < MT; ++i) {
                const uint32_t ad = sb + (arow + i * 16) * A_ROWB + acol * 2;
                ldsm4(ah[i][0], ah[i][1], ah[i][2], ah[i][3], ad);
                ldsm4(al[i][0], al[i][1], al[i][2], al[i][3], ad + A_TILE);
            }
            const int brow = kk + (lane & 15);
#pragma unroll
            for (int j2 = 0; j2 < NT / 2; ++j2) {
                const int bcol = wid_n * WN + j2 * 16 + (lane >> 4) * 8;
                const uint32_t bd = sb + 2 * A_TILE + brow * B_ROWB + bcol * 2;
                ldsm4t(bh[2*j2][0], bh[2*j2][1], bh[2*j2+1][0], bh[2*j2+1][1], bd);
                ldsm4t(bl[2*j2][0], bl[2*j2][1], bl[2*j2+1][0], bl[2*j2+1][1],
                       bd + B_TILE);
            }
#pragma unroll
            for (int i = 0; i < MT; ++i)
#pragma unroll
                for (int j = 0; j < NT; ++j) {
                    mma16816(acc[i][j], ah[i], bh[j]);
                    mma16816(acc[i][j], al[i], bh[j]);
                    mma16816(acc[i][j], ah[i], bl[j]);
                }
        }
        if (ks + 2 < NKI) load_stage(ks + 2, (ks + 2) % 3);
    }

    // -------- epilogue --------
    const int gid = lane >> 2, tig = lane & 3;
    const long long crow0 = (long long)(m0 / c_cr) * c_cs + (m0 % c_cr);

    auto epival = [&](float a, long long ci, long long li, int col) -> float {
        if (EPI == 0) return a;
        if (EPI == 1) return sigmoidf_(a + aux0[col]);
        if (EPI == 2) return aux1[ci] + aux2[li] * a;
        float s = sigmoidf_(a + aux0[col]);
        return s * aux1[ci] + (1.0f - s) * aux2[ci];
    };

#pragma unroll
    for (int i = 0; i < MT; ++i) {
        const int r = wid_m * WM + i * 16 + gid;
#pragma unroll
        for (int j = 0; j < NT; ++j) {
            const int col = n0 + wid_n * WN + j * 8 + 2 * tig;
#pragma unroll
            for (int half = 0; half < 2; ++half) {
                const int rr = r + half * 8;
                const long long ci = (crow0 + rr) * (long long)N + col;
                const long long li = (long long)(m0 + rr) * N + col;
                float2 v;
                v.x = epival(acc[i][j][2 * half + 0], ci, li, col);
                v.y = epival(acc[i][j][2 * half + 1], ci + 1, li + 1, col + 1);
                *reinterpret_cast<float2*>(C + ci) = v;
            }
        }
    }
}

// ---------------- attention: one block per (q, head, batch) -----------------
__global__ void attn_k(const float* __restrict__ Q, const float* __restrict__ Km,
                       const float* __restrict__ V, float* __restrict__ O,
                       int Lq, int Lk, float scale) {
    const int q = blockIdx.x, h = blockIdx.y, b = blockIdx.z;
    const int tid = threadIdx.x;

    __shared__ float qs[HDIM];
    __shared__ float sc[1024];
    __shared__ float red[128];

    const float* qp = Q + ((long long)(b * Lq + q)) * DD + h * HDIM;
    for (int d = tid; d < HDIM; d += 128) qs[d] = qp[d];
    __syncthreads();

    const float4* q4 = reinterpret_cast<const float4*>(qs);

    float lmax = -1e30f;
    for (int j = tid; j < Lk; j += 128) {
        const float4* k4 = reinterpret_cast<const float4*>(
            Km + ((long long)(b * Lk + j)) * DD + h * HDIM);
        float s = 0.0f;
#pragma unroll 8
        for (int d = 0; d < HDIM / 4; ++d) {
            float4 a = q4[d], kb = k4[d];
            s += a.x * kb.x + a.y * kb.y + a.z * kb.z + a.w * kb.w;
        }
        s *= scale;
        sc[j] = s;
        lmax = fmaxf(lmax, s);
    }
    red[tid] = lmax;
    __syncthreads();
    for (int o = 64; o > 0; o >>= 1) {
        if (tid < o) red[tid] = fmaxf(red[tid], red[tid + o]);
        __syncthreads();
    }
    const float gmax = red[0];
    __syncthreads();

    float lsum = 0.0f;
    for (int j = tid; j < Lk; j += 128) {
        float e = __expf(sc[j] - gmax);
        sc[j] = e;
        lsum += e;
    }
    red[tid] = lsum;
    __syncthreads();
    for (int o = 64; o > 0; o >>= 1) {
        if (tid < o) red[tid] += red[tid + o];
        __syncthreads();
    }
    const float inv = 1.0f / red[0];
    __syncthreads();

    float* op = O + ((long long)(b * Lq + q)) * DD + h * HDIM;
    for (int d = tid; d < HDIM; d += 128) {
        float acc = 0.0f;
        const float* vp = V + ((long long)b * Lk) * DD + h * HDIM + d;
        for (int j = 0; j < Lk; ++j) acc += sc[j] * vp[(long long)j * DD];
        op[d] = acc * inv;
    }
}

// ---------------- concat [mem, new_mem] -------------------------------------
__global__ void concat_k(const float* __restrict__ a, const float* __restrict__ b,
                         float* __restrict__ c, int rows, int d) {
    int idx = blockIdx.x * blockDim.x + threadIdx.x;
    int total = rows * 2 * d;
    if (idx >= total) return;
    int r = idx / (2 * d);
    int col = idx % (2 * d);
    c[idx] = (col < d) ? a[(long long)r * d + col] : b[(long long)r * d + col - d];
}

// ---------------- host orchestration ----------------------------------------
extern "C" void kernel_launch(void* const* d_in, const int* in_sizes, int n_in,
                              void* d_out, int out_size) {
    const float* hid      = (const float*)d_in[0];
    const float* init_mem = (const float*)d_in[1];
    const float* wq_r     = (const float*)d_in[2];
    const float* wk_r     = (const float*)d_in[3];
    const float* wv_r     = (const float*)d_in[4];
    const float* wo_r     = (const float*)d_in[5];
    const float* wg_r     = (const float*)d_in[6];
    const float* bg_r     = (const float*)d_in[7];
    const float* wqueries = (const float*)d_in[8];
    const float* wq_w     = (const float*)d_in[9];
    const float* wk_w     = (const float*)d_in[10];
    const float* wv_w     = (const float*)d_in[11];
    const float* wo_w     = (const float*)d_in[12];
    const float* wg_w     = (const float*)d_in[13];
    const float* bg_w     = (const float*)d_in[14];
    float* out = (float*)d_out;

    float *qr, *ctx, *gate, *kw, *vw, *memA, *memB, *kr, *vr, *qw, *aw, *nm, *cat;
    __nv_bfloat16 *whi, *wlo, *ahi, *alo, *chi, *clo, *shi, *slo;
    cudaGetSymbolAddress((void**)&qr,   g_qr);
    cudaGetSymbolAddress((void**)&ctx,  g_ctx);
    cudaGetSymbolAddress((void**)&gate, g_gate);
    cudaGetSymbolAddress((void**)&kw,   g_kw);
    cudaGetSymbolAddress((void**)&vw,   g_vw);
    cudaGetSymbolAddress((void**)&memA, g_memA);
    cudaGetSymbolAddress((void**)&memB, g_memB);
    cudaGetSymbolAddress((void**)&kr,   g_kr);
    cudaGetSymbolAddress((void**)&vr,   g_vr);
    cudaGetSymbolAddress((void**)&qw,   g_qw);
    cudaGetSymbolAddress((void**)&aw,   g_aw);
    cudaGetSymbolAddress((void**)&nm,   g_nm);
    cudaGetSymbolAddress((void**)&cat,  g_cat);
    cudaGetSymbolAddress((void**)&whi,  g_whi);
    cudaGetSymbolAddress((void**)&wlo,  g_wlo);
    cudaGetSymbolAddress((void**)&ahi,  g_ahi);
    cudaGetSymbolAddress((void**)&alo,  g_alo);
    cudaGetSymbolAddress((void**)&chi,  g_chi);
    cudaGetSymbolAddress((void**)&clo,  g_clo);
    cudaGetSymbolAddress((void**)&shi,  g_shi);
    cudaGetSymbolAddress((void**)&slo,  g_slo);

    // dynamic smem limits for the GEMM instantiations
    constexpr int SMEM_BIG = 3 * (2 * 128 * (BKT * 2 + 16) + 2 * BKT * (128 * 2 + 16));
    constexpr int SMEM_SM  = 3 * (2 * 64  * (BKT * 2 + 16) + 2 * BKT * (128 * 2 + 16));
    cudaFuncSetAttribute(mma_gemm<128,128,64,32,0>, cudaFuncAttributeMaxDynamicSharedMemorySize, SMEM_BIG);
    cudaFuncSetAttribute(mma_gemm<128,128,64,32,1>, cudaFuncAttributeMaxDynamicSharedMemorySize, SMEM_BIG);
    cudaFuncSetAttribute(mma_gemm<128,128,64,32,2>, cudaFuncAttributeMaxDynamicSharedMemorySize, SMEM_BIG);
    cudaFuncSetAttribute(mma_gemm<64,128,32,32,0>,  cudaFuncAttributeMaxDynamicSharedMemorySize, SMEM_SM);
    cudaFuncSetAttribute(mma_gemm<64,128,32,32,3>,  cudaFuncAttributeMaxDynamicSharedMemorySize, SMEM_SM);

    const float scale = 0.05590169943749474f;  // 1/sqrt(320)
    const size_t memBytes = (size_t)MMEM * DD * sizeof(float);
    const int MBIG = BATCH * SEGL;   // 2048
    const int MSM  = BATCH * MMEM;   // 256

    dim3 gBig(DD / 128, MBIG / 128);   // (20, 16)
    dim3 gSm (DD / 128, MSM / 64);     // (20, 4)
    dim3 gQw (DD / 128, MMEM / 64);    // (20, 2)

    auto splitL = [&](const float* src, __nv_bfloat16* h, __nv_bfloat16* l,
                      int rows, int Kd, int cr, long long cs) {
        split2d<<<dim3(Kd / 256, rows), 256>>>(src, h, l, Kd, cr, cs);
    };

    // --- weight splits (dense) ---------------------------------------------
    splitL(wq_r, whi + OW_QR, wlo + OW_QR, DD, DD, DD, 0);
    splitL(wk_r, whi + OW_KR, wlo + OW_KR, DD, DD, DD, 0);
    splitL(wv_r, whi + OW_VR, wlo + OW_VR, DD, DD, DD, 0);
    splitL(wo_r, whi + OW_OR, wlo + OW_OR, DD, DD, DD, 0);
    splitL(wg_r, whi + OW_GR, wlo + OW_GR, DD, DD, DD, 0);
    splitL(wq_w, whi + OW_QW, wlo + OW_QW, DD, DD, DD, 0);
    splitL(wk_w, whi + OW_KW, wlo + OW_KW, DD, DD, DD, 0);
    splitL(wv_w, whi + OW_VW, wlo + OW_VW, DD, DD, DD, 0);
    splitL(wo_w, whi + OW_OW, wlo + OW_OW, DD, DD, DD, 0);
    splitL(wg_w, whi + OW_GW, wlo + OW_GW, 2 * DD, DD, 2 * DD, 0);

    // --- pre-loop: qw = write_queries @ wq_w, duplicated for batch ----------
    splitL(wqueries, shi, slo, MMEM, DD, MMEM, 0);
    mma_gemm<64,128,32,32,0><<<gQw, 256, SMEM_SM>>>(shi, slo, whi + OW_QW, wlo + OW_QW,
                                                    qw, MMEM, DD, DD, MMEM, 0,
                                                    nullptr, nullptr, nullptr);
    cudaMemcpyAsync(qw + (size_t)MMEM * DD, qw, memBytes, cudaMemcpyDeviceToDevice, 0);

    cudaMemcpyAsync(memB, init_mem, memBytes, cudaMemcpyDeviceToDevice, 0);
    cudaMemcpyAsync(memB + (size_t)MMEM * DD, init_mem, memBytes,
                    cudaMemcpyDeviceToDevice, 0);

    float* mem_cur = memB;

    for (int i = 0; i < NSEG; ++i) {
        const float* segp = hid + (long long)i * SEGL * DD;
        float* outp = out + (long long)i * SEGL * DD;

        // split seg (chunked rows: 1024-row chunks, stride 4096)
        splitL(segp, ahi, alo, MBIG, DD, SEGL, STOT);
        // q_r = seg @ wq_r
        mma_gemm<128,128,64,32,0><<<gBig, 256, SMEM_BIG>>>(ahi, alo,
            whi + OW_QR, wlo + OW_QR, qr, MBIG, DD, DD, MBIG, 0,
            nullptr, nullptr, nullptr);
        // gate = sigmoid(seg @ wg_r + bg_r)
        mma_gemm<128,128,64,32,1><<<gBig, 256, SMEM_BIG>>>(ahi, alo,
            whi + OW_GR, wlo + OW_GR, gate, MBIG, DD, DD, MBIG, 0,
            bg_r, nullptr, nullptr);
        // k_r, v_r = mem @ wk_r / wv_r
        splitL(mem_cur, shi, slo, MSM, DD, MSM, 0);
        mma_gemm<64,128,32,32,0><<<gSm, 256, SMEM_SM>>>(shi, slo,
            whi + OW_KR, wlo + OW_KR, kr, MSM, DD, DD, MSM, 0,
            nullptr, nullptr, nullptr);
        mma_gemm<64,128,32,32,0><<<gSm, 256, SMEM_SM>>>(shi, slo,
            whi + OW_VR, wlo + OW_VR, vr, MSM, DD, DD, MSM, 0,
            nullptr, nullptr, nullptr);
        // read attention
        attn_k<<<dim3(SEGL, NH, BATCH), 128>>>(qr, kr, vr, ctx, SEGL, MMEM, scale);
        // h = seg + gate * (ctx @ wo_r)  -> into d_out (chunked C)
        splitL(ctx, chi, clo, MBIG, DD, MBIG, 0);
        mma_gemm<128,128,64,32,2><<<gBig, 256, SMEM_BIG>>>(chi, clo,
            whi + OW_OR, wlo + OW_OR, outp, MBIG, DD, DD, SEGL, STOT,
            nullptr, segp, gate);
        // k_w, v_w = h @ wk_w / wv_w
        splitL(outp, ahi, alo, MBIG, DD, SEGL, STOT);
        mma_gemm<128,128,64,32,0><<<gBig, 256, SMEM_BIG>>>(ahi, alo,
            whi + OW_KW, wlo + OW_KW, kw, MBIG, DD, DD, MBIG, 0,
            nullptr, nullptr, nullptr);
        mma_gemm<128,128,64,32,0><<<gBig, 256, SMEM_BIG>>>(ahi, alo,
            whi + OW_VW, wlo + OW_VW, vw, MBIG, DD, DD, MBIG, 0,
            nullptr, nullptr, nullptr);
        // write attention
        attn_k<<<dim3(MMEM, NH, BATCH), 128>>>(qw, kw, vw, aw, MMEM, SEGL, scale);
        // new_mem = aw @ wo_w
        splitL(aw, shi, slo, MSM, DD, MSM, 0);
        mma_gemm<64,128,32,32,0><<<gSm, 256, SMEM_SM>>>(shi, slo,
            whi + OW_OW, wlo + OW_OW, nm, MSM, DD, DD, MSM, 0,
            nullptr, nullptr, nullptr);
        // memory update
        if (i == 0) {
            cudaMemcpyAsync(memA, nm, (size_t)MSM * DD * sizeof(float),
                            cudaMemcpyDeviceToDevice, 0);
            mem_cur = memA;
        } else {
            float* mem_next = (mem_cur == memA) ? memB : memA;
            int total = MSM * 2 * DD;
            concat_k<<<(total + 255) / 256, 256>>>(mem_cur, nm, cat, MSM, DD);
            splitL(cat, shi, slo, MSM, 2 * DD, MSM, 0);
            mma_gemm<64,128,32,32,3><<<gSm, 256, SMEM_SM>>>(shi, slo,
                whi + OW_GW, wlo + OW_GW, mem_next, MSM, DD, 2 * DD, MSM, 0,
                bg_w, nm, mem_cur);
            mem_cur = mem_next;
        }
    }
}